// round 7
// baseline (speedup 1.0000x reference)
#include <cuda_runtime.h>

#define N_   64
#define C_   128
#define T_   2048
#define EPS_ 1e-5f

// warps per half: 16 tchunks * 64 n * 4 warps = 4096; 4 partial lanes each.
#define NWARPS 4096
#define PARTW  4
#define NPART  (NWARPS * PARTW)   // 16384

__device__ float g_ps[C_][NPART];
__device__ float g_pq[C_][NPART];
__device__ float g_scale[C_];
__device__ float g_bias [C_];

// Channel sweep: thread owns ONE time column t0.
// y[c'] = x[c', t - sh(c')], sh(c') = c'%9 - 4.  out[c] = sum_s w[c,s]*y[c-4+s].
// Ring of 9 y-values; all ring indices / shifts are compile-time immediates.
template<int CLO, int WRITE, int SAFE>
__device__ __forceinline__ void sweep(
    const float* __restrict__ xn, float* __restrict__ outn,
    const float* __restrict__ sw, const float* __restrict__ ssc,
    const float* __restrict__ sbi, int t0, int bid4, int lane)
{
    const float* xt = xn + t0;
    float* ot = outn + t0;   // only dereferenced when WRITE

    float y0[9];
    #pragma unroll
    for (int k = 0; k < 9; ++k) y0[k] = 0.f;

    #pragma unroll
    for (int jj = 0; jj < 72; ++jj) {
        const int jg = CLO - 4 + jj;           // source channel being loaded
        if (jg >= 0 && jg < C_) {              // static after unroll
            const int m    = ((jg % 9) + 9) % 9;
            const int sh   = m - 4;
            const int off  = jg * T_ - sh;     // immediate offset
            if (SAFE) {
                y0[m] = xt[off];
            } else {
                const int i = t0 - sh;
                y0[m] = ((unsigned)i < T_) ? xt[off] : 0.f;
            }
        } else if (jg >= C_) {
            // Top channel pad: slot would otherwise hold stale channel jg-9.
            y0[jg % 9] = 0.f;
        }
        if (jj >= 8) {                          // output channel c = CLO + jj - 8
            const int r = jj - 8;               // local row [0,64)
            const int c = CLO + r;
            const float4 wA = *(const float4*)(sw + r * 12);
            const float4 wB = *(const float4*)(sw + r * 12 + 4);
            const float  w8 = sw[r * 12 + 8];
            const int sb = (((jg - 8) % 9) + 9) % 9;   // slot of y[c-4]
            float a0 = 0.f;
            #define TAP(s, ws) { const int sl = (sb + (s)) % 9;  \
                a0 = fmaf((ws), y0[sl], a0); }
            TAP(0, wA.x) TAP(1, wA.y) TAP(2, wA.z) TAP(3, wA.w)
            TAP(4, wB.x) TAP(5, wB.y) TAP(6, wB.z) TAP(7, wB.w)
            TAP(8, w8)
            #undef TAP

            if (WRITE) {
                ot[c * T_] = fmaxf(fmaf(a0, ssc[r], sbi[r]), 0.f);
            } else {
                float s = a0;
                float q = a0 * a0;
                // 3-stage butterfly: lane l holds sum over lanes == l (mod 4)
                s += __shfl_xor_sync(0xffffffffu, s, 16);
                q += __shfl_xor_sync(0xffffffffu, q, 16);
                s += __shfl_xor_sync(0xffffffffu, s, 8);
                q += __shfl_xor_sync(0xffffffffu, q, 8);
                s += __shfl_xor_sync(0xffffffffu, s, 4);
                q += __shfl_xor_sync(0xffffffffu, q, 4);
                if (lane < PARTW) {
                    g_ps[c][bid4 + lane] = s;
                    g_pq[c][bid4 + lane] = q;
                }
            }
        }
    }
}

template<int WRITE>
__global__ void __launch_bounds__(128, 12)
conv_kernel(const float* __restrict__ x, const float* __restrict__ cw,
            float* __restrict__ out)
{
    __shared__ float sw[64 * 12];
    __shared__ float ssc[64], sbi[64];

    const int tid    = threadIdx.x;
    const int tchunk = blockIdx.x;     // 0..15 (128 t each)
    const int n      = blockIdx.y;     // 0..63
    const int half   = blockIdx.z;     // 0..1
    const int clo    = half * 64;

    for (int i = tid; i < 64 * 9; i += 128) {
        int r = i / 9, s = i - r * 9;
        sw[r * 12 + s] = cw[(clo + r) * 9 + s];
    }
    if (WRITE && tid < 64) {
        ssc[tid] = g_scale[clo + tid];
        sbi[tid] = g_bias [clo + tid];
    }
    __syncthreads();

    const int t0   = tchunk * 128 + tid;
    const int warp = tid >> 5, lane = tid & 31;
    const int tw   = tchunk * 128 + warp * 32;
    // All loads in range iff tw-4 >= 0 and tw+31+4 <= T-1.
    const bool safe = (tw >= 4) && (tw + 31 + 4 <= T_ - 1);
    const int bid4 = (((n * 16 + tchunk) * 4 + warp) * PARTW);

    const float* xn   = x   + (size_t)n * C_ * T_;
    float*       outn = out + (size_t)n * C_ * T_;

    if (half == 0) {
        if (safe) sweep<0, WRITE, 1>(xn, outn, sw, ssc, sbi, t0, bid4, lane);
        else      sweep<0, WRITE, 0>(xn, outn, sw, ssc, sbi, t0, bid4, lane);
    } else {
        if (safe) sweep<64, WRITE, 1>(xn, outn, sw, ssc, sbi, t0, bid4, lane);
        else      sweep<64, WRITE, 0>(xn, outn, sw, ssc, sbi, t0, bid4, lane);
    }
}

__global__ void __launch_bounds__(256)
finalize_kernel(const float* __restrict__ gamma, const float* __restrict__ beta)
{
    __shared__ float rs[256], rq[256];
    const int c = blockIdx.x;
    const int tid = threadIdx.x;
    float s = 0.f, q = 0.f;
    #pragma unroll 8
    for (int j = tid; j < NPART; j += 256) {
        s += g_ps[c][j];
        q += g_pq[c][j];
    }
    rs[tid] = s; rq[tid] = q;
    __syncthreads();
    #pragma unroll
    for (int off = 128; off > 0; off >>= 1) {
        if (tid < off) { rs[tid] += rs[tid + off]; rq[tid] += rq[tid + off]; }
        __syncthreads();
    }
    if (tid == 0) {
        const float invNT = 1.f / (float)(N_ * T_);
        const float m   = rs[0] * invNT;
        const float v   = rq[0] * invNT - m * m;
        const float inv = rsqrtf(v + EPS_);
        const float sc  = gamma[c] * inv;
        g_scale[c] = sc;
        g_bias [c] = beta[c] - m * sc;
    }
}

extern "C" void kernel_launch(void* const* d_in, const int* in_sizes, int n_in,
                              void* d_out, int out_size)
{
    const float* x     = (const float*)d_in[0];
    const float* cw    = (const float*)d_in[1];
    const float* gamma = (const float*)d_in[2];
    const float* beta  = (const float*)d_in[3];
    float* out = (float*)d_out;

    dim3 grid(16, N_, 2);
    conv_kernel<0><<<grid, 128>>>(x, cw, nullptr);
    finalize_kernel<<<C_, 256>>>(gamma, beta);
    conv_kernel<1><<<grid, 128>>>(x, cw, out);
}

// round 9
// speedup vs baseline: 1.1135x; 1.1135x over previous
#include <cuda_runtime.h>

#define N_   64
#define C_   128
#define T_   2048
#define EPS_ 1e-5f

// warps per half: 16 tchunks * 64 n * 2 warps = 2048; 8 partial lanes each.
#define PARTW  8
#define NPART  (2048 * PARTW)   // 16384

__device__ float g_ps[C_][NPART];
__device__ float g_pq[C_][NPART];
__device__ float g_scale[C_];
__device__ float g_bias [C_];

// Channel sweep: thread owns 2 time columns (t0, t0+64).
// y[c'] = x[c', t - sh(c')], sh(c') = c'%9 - 4.  out[c] = sum_s w[c,s]*y[c-4+s].
// Ring of 9 y-values per column; ring indices / shifts are compile-time.
template<int CLO, int WRITE, int SAFE>
__device__ __forceinline__ void sweep(
    const float* __restrict__ xn, float* __restrict__ outn,
    const float* __restrict__ sw, const float* __restrict__ ssc,
    const float* __restrict__ sbi, int t0, int bid8, int lane)
{
    const float* xt = xn + t0;
    float* ot = outn + t0;   // only dereferenced when WRITE

    float y0[9], y1[9];
    #pragma unroll
    for (int k = 0; k < 9; ++k) { y0[k] = 0.f; y1[k] = 0.f; }

    #pragma unroll
    for (int jj = 0; jj < 72; ++jj) {
        const int jg = CLO - 4 + jj;           // source channel being loaded
        if (jg >= 0 && jg < C_) {              // static after unroll
            const int m    = ((jg % 9) + 9) % 9;
            const int sh   = m - 4;
            const int off  = jg * T_ - sh;     // immediate offset
            if (SAFE) {
                y0[m] = xt[off];
                y1[m] = xt[off + 64];
            } else {
                int i = t0 - sh;
                y0[m] = ((unsigned)i < T_) ? xt[off]      : 0.f; i += 64;
                y1[m] = ((unsigned)i < T_) ? xt[off + 64] : 0.f;
            }
        } else if (jg >= C_) {
            // Top channel pad: slot would otherwise hold stale channel jg-9.
            const int m = jg % 9;
            y0[m] = 0.f; y1[m] = 0.f;
        }
        if (jj >= 8) {                          // output channel c = CLO + jj - 8
            const int r = jj - 8;               // local row [0,64)
            const int c = CLO + r;
            const float4 wA = *(const float4*)(sw + r * 12);
            const float4 wB = *(const float4*)(sw + r * 12 + 4);
            const float  w8 = sw[r * 12 + 8];
            const int sb = (((jg - 8) % 9) + 9) % 9;   // slot of y[c-4]
            float a0 = 0.f, a1 = 0.f;
            #define TAP(s, ws) { const int sl = (sb + (s)) % 9;            \
                a0 = fmaf((ws), y0[sl], a0); a1 = fmaf((ws), y1[sl], a1); }
            TAP(0, wA.x) TAP(1, wA.y) TAP(2, wA.z) TAP(3, wA.w)
            TAP(4, wB.x) TAP(5, wB.y) TAP(6, wB.z) TAP(7, wB.w)
            TAP(8, w8)
            #undef TAP

            if (WRITE) {
                const float sc = ssc[r];
                const float bi = sbi[r];
                ot[c * T_     ] = fmaxf(fmaf(a0, sc, bi), 0.f);
                ot[c * T_ + 64] = fmaxf(fmaf(a1, sc, bi), 0.f);
            } else {
                float s = a0 + a1;
                float q = fmaf(a0, a0, a1 * a1);
                // 2-stage butterfly: lane l holds sum over lanes == l (mod 8)
                s += __shfl_xor_sync(0xffffffffu, s, 16);
                q += __shfl_xor_sync(0xffffffffu, q, 16);
                s += __shfl_xor_sync(0xffffffffu, s, 8);
                q += __shfl_xor_sync(0xffffffffu, q, 8);
                if (lane < PARTW) {
                    g_ps[c][bid8 + lane] = s;
                    g_pq[c][bid8 + lane] = q;
                }
            }
        }
    }
}

template<int WRITE>
__global__ void __launch_bounds__(64, 16)
conv_kernel(const float* __restrict__ x, const float* __restrict__ cw,
            float* __restrict__ out)
{
    __shared__ float sw[64 * 12];
    __shared__ float ssc[64], sbi[64];

    const int tid    = threadIdx.x;    // 0..63
    const int tchunk = blockIdx.x;     // 0..15 (128 t each)
    const int n      = blockIdx.y;     // 0..63
    const int half   = blockIdx.z;     // 0..1
    const int clo    = half * 64;

    for (int i = tid; i < 64 * 9; i += 64) {
        int r = i / 9, s = i - r * 9;
        sw[r * 12 + s] = cw[(clo + r) * 9 + s];
    }
    if (WRITE) {
        ssc[tid] = g_scale[clo + tid];
        sbi[tid] = g_bias [clo + tid];
    }
    __syncthreads();

    const int t0   = tchunk * 128 + tid;
    const int warp = tid >> 5, lane = tid & 31;
    const int tw   = tchunk * 128 + warp * 32;
    // All loads in range iff tw-4 >= 0 and tw+31+64+4 <= T-1.
    const bool safe = (tw >= 4) && (tw + 31 + 64 + 4 <= T_ - 1);
    const int bid8 = (((n * 16 + tchunk) * 2 + warp) * PARTW);

    const float* xn   = x   + (size_t)n * C_ * T_;
    float*       outn = out + (size_t)n * C_ * T_;

    if (half == 0) {
        if (safe) sweep<0, WRITE, 1>(xn, outn, sw, ssc, sbi, t0, bid8, lane);
        else      sweep<0, WRITE, 0>(xn, outn, sw, ssc, sbi, t0, bid8, lane);
    } else {
        if (safe) sweep<64, WRITE, 1>(xn, outn, sw, ssc, sbi, t0, bid8, lane);
        else      sweep<64, WRITE, 0>(xn, outn, sw, ssc, sbi, t0, bid8, lane);
    }
}

__global__ void __launch_bounds__(256)
finalize_kernel(const float* __restrict__ gamma, const float* __restrict__ beta)
{
    __shared__ float rs[256], rq[256];
    const int c = blockIdx.x;
    const int tid = threadIdx.x;
    float s = 0.f, q = 0.f;
    #pragma unroll 8
    for (int j = tid; j < NPART; j += 256) {
        s += g_ps[c][j];
        q += g_pq[c][j];
    }
    rs[tid] = s; rq[tid] = q;
    __syncthreads();
    #pragma unroll
    for (int off = 128; off > 0; off >>= 1) {
        if (tid < off) { rs[tid] += rs[tid + off]; rq[tid] += rq[tid + off]; }
        __syncthreads();
    }
    if (tid == 0) {
        const float invNT = 1.f / (float)(N_ * T_);
        const float m   = rs[0] * invNT;
        const float v   = rq[0] * invNT - m * m;
        const float inv = rsqrtf(v + EPS_);
        const float sc  = gamma[c] * inv;
        g_scale[c] = sc;
        g_bias [c] = beta[c] - m * sc;
    }
}

extern "C" void kernel_launch(void* const* d_in, const int* in_sizes, int n_in,
                              void* d_out, int out_size)
{
    const float* x     = (const float*)d_in[0];
    const float* cw    = (const float*)d_in[1];
    const float* gamma = (const float*)d_in[2];
    const float* beta  = (const float*)d_in[3];
    float* out = (float*)d_out;

    dim3 grid(16, N_, 2);
    conv_kernel<0><<<grid, 64>>>(x, cw, nullptr);
    finalize_kernel<<<C_, 256>>>(gamma, beta);
    conv_kernel<1><<<grid, 64>>>(x, cw, out);
}